// round 12
// baseline (speedup 1.0000x reference)
#include <cuda_runtime.h>
#include <cstdint>

// Blocked Hadamard transform, BLOCK = 256 = 4^4.
// H4 = ones(4) - 2*antidiag ; H = kron(H4 x4) / 16.
// In-block index i = i0 + 4*i1 + 16*i2 + 64*i3 (base-4 digits).
//
// Warp handles 1024 consecutive floats (4 blocks) as 8 float4 chunks/thread:
//   idx = 4*lane + e + 128*c,  e in [0,4), c in [0,8)
//   -> i0 = e (register-local), i1 = lane[1:0], i2 = lane[3:2],
//      i3 = (c&1)<<1 | lane[4], block = c>>1.
// All 8 loads are front-batched (MLP_p1 = 8, 4KB in flight per warp) and every
// global access is a warp-contiguous LDG.128/STG.128 (512B per instruction).
//
// Per-thread stage costs: i0 free (fused into load), i3 split-digit butterfly
// (1 SHFL per chunk pair on the difference: 16), i1/i2 two-shuffle identity
// (64 each over 32 values): 144 SHFL per thread for 32 values (4.5/value, floor).

__global__ void __launch_bounds__(256) hadamard256_kernel(
    const float* __restrict__ x, float* __restrict__ out)
{
    const unsigned warp_global = blockIdx.x * 8u + (threadIdx.x >> 5);
    const unsigned lane = threadIdx.x & 31u;
    // base in float4 units; warp accesses are contiguous 512B per instruction
    const size_t base4 = (size_t)warp_global * 256u + lane;

    const float4* xp = reinterpret_cast<const float4*>(x) + base4;

    float4 v[8];
    #pragma unroll
    for (int c = 0; c < 8; c++)
        v[c] = __ldcs(xp + 32 * c);

    // ---- Stage i0 (register-local H4 within each float4) ----
    #pragma unroll
    for (int c = 0; c < 8; c++) {
        float4 t = v[c];
        float s01 = t.x + t.y, d01 = t.x - t.y;
        float s23 = t.z + t.w, d23 = t.z - t.w;
        v[c].x = s01 + d23;   //  x0+x1+x2-x3
        v[c].y = s01 - d23;   //  x0+x1-x2+x3
        v[c].z = d01 + s23;   //  x0-x1+x2+x3
        v[c].w = s23 - d01;   // -x0+x1+x2+x3
    }

    // ---- Stage i3: split digit (low bit = lane bit 4, high bit = c bit 0).
    // Pairs (2p, 2p+1); ONE shuffle per element pair:
    //   s = A+B; d = A-B; ds = shfl_xor(d,16); A' = s+ds; B' = s-ds
    #pragma unroll
    for (int p = 0; p < 4; p++) {
        float* A = reinterpret_cast<float*>(&v[2 * p]);
        float* B = reinterpret_cast<float*>(&v[2 * p + 1]);
        #pragma unroll
        for (int e = 0; e < 4; e++) {
            float s = A[e] + B[e];
            float d = A[e] - B[e];
            float ds = __shfl_xor_sync(0xffffffffu, d, 16);
            A[e] = s + ds;
            B[e] = s - ds;
        }
    }

    // ---- Stage i1: lane bits [1:0], 2-shuffle identity ----
    {
        float* f = reinterpret_cast<float*>(v);
        #pragma unroll
        for (int j = 0; j < 32; j++) {
            float a  = __shfl_xor_sync(0xffffffffu, f[j], 1);
            float s  = f[j] + a;
            float d  = f[j] - a;
            float d2 = __shfl_xor_sync(0xffffffffu, d, 2);
            f[j] = s + d2;
        }
    }

    // ---- Stage i2: lane bits [3:2], 2-shuffle identity, fold 1/16 ----
    {
        float* f = reinterpret_cast<float*>(v);
        #pragma unroll
        for (int j = 0; j < 32; j++) {
            float a  = __shfl_xor_sync(0xffffffffu, f[j], 4);
            float s  = f[j] + a;
            float d  = f[j] - a;
            float d2 = __shfl_xor_sync(0xffffffffu, d, 8);
            f[j] = (s + d2) * 0.0625f;
        }
    }

    float4* op = reinterpret_cast<float4*>(out) + base4;
    #pragma unroll
    for (int c = 0; c < 8; c++)
        __stcs(op + 32 * c, v[c]);
}

extern "C" void kernel_launch(void* const* d_in, const int* in_sizes, int n_in,
                              void* d_out, int out_size)
{
    const float* x = (const float*)d_in[0];
    float* out = (float*)d_out;

    // out_size = 2*4096*8192 = 67,108,864 floats.
    // One warp handles 1024 floats; 8 warps (256 threads) per CTA -> 8192 floats/CTA.
    const long long n = (long long)out_size;
    const int cta_elems = 8192;
    const int grid = (int)(n / cta_elems);   // 8192, exact

    hadamard256_kernel<<<grid, 256>>>(x, out);
}